// round 8
// baseline (speedup 1.0000x reference)
#include <cuda_runtime.h>
#include <cfloat>
#include <math.h>

#define B_  1024
#define N_  50000
#define D_  256
#define MA_ 200
#define K_  8

// ---------- device scratch ----------
__device__ float g_qh[B_ * D_];
__device__ float g_mh[(size_t)N_ * D_];
__device__ float g_qhh[B_ * D_];                 // tf32 hi split
__device__ float g_qhl[B_ * D_];                 // tf32 lo split
__device__ float g_mhh[(size_t)N_ * D_];
__device__ float g_mhl[(size_t)N_ * D_];
__device__ float g_qsq[B_];
__device__ float g_msq[N_];
__device__ float g_arg[(size_t)B_ * N_];         // ~195 MB

// ---------- helpers ----------
__device__ __forceinline__ unsigned long long pk2(float x, float y) {
    unsigned long long u;
    asm("mov.b64 %0, {%1,%2};" : "=l"(u) : "f"(x), "f"(y));
    return u;
}
__device__ __forceinline__ float2 up2(unsigned long long u) {
    float2 v;
    asm("mov.b64 {%0,%1}, %2;" : "=f"(v.x), "=f"(v.y) : "l"(u));
    return v;
}
__device__ __forceinline__ void fma2(unsigned long long& c, unsigned long long a,
                                     unsigned long long b) {
    asm("fma.rn.f32x2 %0, %1, %2, %3;" : "=l"(c) : "l"(a), "l"(b), "l"(c));
}
__device__ __forceinline__ unsigned long long umin64(unsigned long long a,
                                                     unsigned long long b) {
    return a < b ? a : b;
}
__device__ __forceinline__ float tf32r(float x) {
    float r;
    asm("cvt.rna.tf32.f32 %0, %1;" : "=f"(r) : "f"(x));
    return r;
}
// D = A(16x8 tf32, row) @ B(8x8 tf32, col) + D, fp32 accum
__device__ __forceinline__ void mma_tf32(float* d, const float* a, const float* b) {
    asm volatile(
        "mma.sync.aligned.m16n8k8.row.col.f32.tf32.tf32.f32 "
        "{%0,%1,%2,%3}, {%4,%5,%6,%7}, {%8,%9}, {%0,%1,%2,%3};"
        : "+f"(d[0]), "+f"(d[1]), "+f"(d[2]), "+f"(d[3])
        : "f"(a[0]), "f"(a[1]), "f"(a[2]), "f"(a[3]), "f"(b[0]), "f"(b[1]));
}

// fp32 micro-kernel for transform (8q x 4c per thread)
#define MICRO_KK(kk)                                                          \
    {                                                                         \
        float4 q0 = *reinterpret_cast<const float4*>(&As[(kk) * 64 + w8]);    \
        float4 q1 = *reinterpret_cast<const float4*>(&As[(kk) * 64 + w8 + 4]);\
        ulonglong2 b = *reinterpret_cast<const ulonglong2*>(&Bs[(kk) * 128 + lane4]); \
        unsigned long long a0 = pk2(q0.x, q0.x), a1 = pk2(q0.y, q0.y);        \
        unsigned long long a2 = pk2(q0.z, q0.z), a3 = pk2(q0.w, q0.w);        \
        unsigned long long a4 = pk2(q1.x, q1.x), a5 = pk2(q1.y, q1.y);        \
        unsigned long long a6 = pk2(q1.z, q1.z), a7 = pk2(q1.w, q1.w);        \
        fma2(acc[0][0], a0, b.x); fma2(acc[0][1], a0, b.y);                   \
        fma2(acc[1][0], a1, b.x); fma2(acc[1][1], a1, b.y);                   \
        fma2(acc[2][0], a2, b.x); fma2(acc[2][1], a2, b.y);                   \
        fma2(acc[3][0], a3, b.x); fma2(acc[3][1], a3, b.y);                   \
        fma2(acc[4][0], a4, b.x); fma2(acc[4][1], a4, b.y);                   \
        fma2(acc[5][0], a5, b.x); fma2(acc[5][1], a5, b.y);                   \
        fma2(acc[6][0], a6, b.x); fma2(acc[6][1], a6, b.y);                   \
        fma2(acc[7][0], a7, b.x); fma2(acc[7][1], a7, b.y);                   \
    }

// ================= kernel 1: h = tanh(X @ W + b)  (fp32, unchanged) =================
__global__ void __launch_bounds__(256, 2) k_transform(const float* __restrict__ A,
                                                      const float* __restrict__ W,
                                                      const float* __restrict__ bias,
                                                      int M, int to_mem) {
    __shared__ __align__(16) float As[32 * 64];
    __shared__ __align__(16) float Bs[32 * 128];
    float* __restrict__ out = to_mem ? g_mh : g_qh;

    const int tid = threadIdx.x;
    const int w8 = (tid >> 5) * 8;
    const int lane4 = (tid & 31) * 4;
    const int rbase = blockIdx.x * 64;
    const int cbase = blockIdx.y * 128;

    unsigned long long acc[8][2];
#pragma unroll
    for (int i = 0; i < 8; i++) { acc[i][0] = 0ull; acc[i][1] = 0ull; }

    const int sr = tid & 63;
    const int skq = tid >> 6;
    const int wkw = tid >> 3;
    const int wcs = (tid & 7) * 16;

    for (int ko = 0; ko < D_; ko += 32) {
        {
            int gr = rbase + sr;
            float4 v0 = {0,0,0,0}, v1 = {0,0,0,0};
            if (gr < M) {
                const float4* p = reinterpret_cast<const float4*>(A + (size_t)gr * D_ + ko + skq * 8);
                v0 = p[0]; v1 = p[1];
            }
            float vv[8] = {v0.x,v0.y,v0.z,v0.w,v1.x,v1.y,v1.z,v1.w};
#pragma unroll
            for (int i = 0; i < 8; i++) As[(skq * 8 + i) * 64 + sr] = vv[i];
        }
        {
            const float4* p = reinterpret_cast<const float4*>(W + (size_t)(ko + wkw) * D_ + cbase + wcs);
            float4 w0 = p[0], w1 = p[1], w2 = p[2], w3 = p[3];
            float4* q = reinterpret_cast<float4*>(&Bs[wkw * 128 + wcs]);
            q[0] = w0; q[1] = w1; q[2] = w2; q[3] = w3;
        }
        __syncthreads();
#pragma unroll
        for (int kk = 0; kk < 32; kk++) MICRO_KK(kk)
        __syncthreads();
    }

    const int c0 = cbase + lane4;
    float4 b4 = *reinterpret_cast<const float4*>(bias + c0);
#pragma unroll
    for (int i = 0; i < 8; i++) {
        int r = rbase + w8 + i;
        if (r < M) {
            float2 v0 = up2(acc[i][0]), v1 = up2(acc[i][1]);
            float4 o;
            o.x = tanhf(v0.x + b4.x); o.y = tanhf(v0.y + b4.y);
            o.z = tanhf(v1.x + b4.z); o.w = tanhf(v1.y + b4.w);
            *reinterpret_cast<float4*>(out + (size_t)r * D_ + c0) = o;
        }
    }
}

// ========== kernel 2: Poincare rescale + sumsq + tf32 hi/lo split ==========
__global__ void __launch_bounds__(256) k_normalize(int which, int M) {
    float* __restrict__ h  = which ? g_mh  : g_qh;
    float* __restrict__ sq = which ? g_msq : g_qsq;
    float* __restrict__ hh = which ? g_mhh : g_qhh;
    float* __restrict__ hl = which ? g_mhl : g_qhl;
    int row = blockIdx.x * 8 + (threadIdx.x >> 5);
    if (row >= M) return;
    int lane = threadIdx.x & 31;
    size_t off = (size_t)row * D_ + lane * 8;
    float4* p = reinterpret_cast<float4*>(h + off);
    float4 v0 = p[0], v1 = p[1];
    float s = v0.x*v0.x + v0.y*v0.y + v0.z*v0.z + v0.w*v0.w
            + v1.x*v1.x + v1.y*v1.y + v1.z*v1.z + v1.w*v1.w;
#pragma unroll
    for (int o = 16; o; o >>= 1) s += __shfl_xor_sync(0xffffffffu, s, o);
    float norm = sqrtf(s);
    float scale = (norm > 0.95f) ? (0.95f / norm) : 1.0f;
    float y[8] = {v0.x*scale, v0.y*scale, v0.z*scale, v0.w*scale,
                  v1.x*scale, v1.y*scale, v1.z*scale, v1.w*scale};
    v0.x=y[0]; v0.y=y[1]; v0.z=y[2]; v0.w=y[3];
    v1.x=y[4]; v1.y=y[5]; v1.z=y[6]; v1.w=y[7];
    p[0] = v0; p[1] = v1;
    float hi[8], lo[8];
    float s2 = 0.0f;
#pragma unroll
    for (int i = 0; i < 8; i++) {
        s2 += y[i] * y[i];
        hi[i] = tf32r(y[i]);
        lo[i] = tf32r(y[i] - hi[i]);
    }
#pragma unroll
    for (int o = 16; o; o >>= 1) s2 += __shfl_xor_sync(0xffffffffu, s2, o);
    if (lane == 0) sq[row] = s2;
    float4* ph = reinterpret_cast<float4*>(hh + off);
    float4* pl = reinterpret_cast<float4*>(hl + off);
    ph[0] = make_float4(hi[0],hi[1],hi[2],hi[3]);
    ph[1] = make_float4(hi[4],hi[5],hi[6],hi[7]);
    pl[0] = make_float4(lo[0],lo[1],lo[2],lo[3]);
    pl[1] = make_float4(lo[4],lo[5],lo[6],lo[7]);
}

// ========== kernel 3: distance GEMM (3xTF32 mma.sync) -> arg matrix ==========
// block 64q x 128m, 8 warps (4 q-groups x 2 m-groups); warp = 16q x 64m.
// smem tiles padded to stride 36 -> conflict-free fragment loads.
#define QS 36
__global__ void __launch_bounds__(256, 2) k_dist_mma() {
    __shared__ __align__(16) float Qh[64 * QS];
    __shared__ __align__(16) float Ql[64 * QS];
    __shared__ __align__(16) float Mh[128 * QS];
    __shared__ __align__(16) float Ml[128 * QS];

    const int tid = threadIdx.x;
    const int warp = tid >> 5, lane = tid & 31;
    const int g = lane >> 2, tig = lane & 3;
    const int qw = (warp & 3) * 16;          // warp q offset in block tile
    const int nw = (warp >> 2) * 64;         // warp m offset in block tile
    const int qbase = blockIdx.x * 64;
    const int mb = blockIdx.y * 128;

    float acc[8][4];
#pragma unroll
    for (int j = 0; j < 8; j++)
#pragma unroll
        for (int c = 0; c < 4; c++) acc[j][c] = 0.0f;

    const int sq_ = tid & 63, skq = tid >> 6;      // Q staging: q row, k-quarter(8)
    const int sm_ = tid & 127, smh = tid >> 7;     // M staging: m row, k-half(16)

    for (int ko = 0; ko < D_; ko += 32) {
        {   // Q tiles hi/lo: 64 x 32
            size_t goff = (size_t)(qbase + sq_) * D_ + ko + skq * 8;
            const float4* ph = reinterpret_cast<const float4*>(g_qhh + goff);
            const float4* pl = reinterpret_cast<const float4*>(g_qhl + goff);
            float4 h0 = ph[0], h1 = ph[1], l0 = pl[0], l1 = pl[1];
            float* dh = &Qh[sq_ * QS + skq * 8];
            float* dl = &Ql[sq_ * QS + skq * 8];
            *reinterpret_cast<float4*>(dh)     = h0;
            *reinterpret_cast<float4*>(dh + 4) = h1;
            *reinterpret_cast<float4*>(dl)     = l0;
            *reinterpret_cast<float4*>(dl + 4) = l1;
        }
        {   // M tiles hi/lo: 128 x 32
            int gm = mb + sm_;
            float4 h[4], l[4];
            if (gm < N_) {
                size_t goff = (size_t)gm * D_ + ko + smh * 16;
                const float4* ph = reinterpret_cast<const float4*>(g_mhh + goff);
                const float4* pl = reinterpret_cast<const float4*>(g_mhl + goff);
#pragma unroll
                for (int i = 0; i < 4; i++) { h[i] = ph[i]; l[i] = pl[i]; }
            } else {
                float4 z = {0,0,0,0};
#pragma unroll
                for (int i = 0; i < 4; i++) { h[i] = z; l[i] = z; }
            }
            float* dh = &Mh[sm_ * QS + smh * 16];
            float* dl = &Ml[sm_ * QS + smh * 16];
#pragma unroll
            for (int i = 0; i < 4; i++) {
                *reinterpret_cast<float4*>(dh + 4 * i) = h[i];
                *reinterpret_cast<float4*>(dl + 4 * i) = l[i];
            }
        }
        __syncthreads();
#pragma unroll
        for (int ks = 0; ks < 4; ks++) {
            const int k0 = ks * 8;
            float ah[4], al[4];
            ah[0] = Qh[(qw + g)     * QS + k0 + tig];
            ah[1] = Qh[(qw + g + 8) * QS + k0 + tig];
            ah[2] = Qh[(qw + g)     * QS + k0 + tig + 4];
            ah[3] = Qh[(qw + g + 8) * QS + k0 + tig + 4];
            al[0] = Ql[(qw + g)     * QS + k0 + tig];
            al[1] = Ql[(qw + g + 8) * QS + k0 + tig];
            al[2] = Ql[(qw + g)     * QS + k0 + tig + 4];
            al[3] = Ql[(qw + g + 8) * QS + k0 + tig + 4];
#pragma unroll
            for (int jn = 0; jn < 8; jn++) {
                const int n0 = nw + jn * 8;
                float bh[2], bl[2];
                bh[0] = Mh[(n0 + g) * QS + k0 + tig];
                bh[1] = Mh[(n0 + g) * QS + k0 + tig + 4];
                bl[0] = Ml[(n0 + g) * QS + k0 + tig];
                bl[1] = Ml[(n0 + g) * QS + k0 + tig + 4];
                mma_tf32(acc[jn], ah, bl);   // small terms first
                mma_tf32(acc[jn], al, bh);
                mma_tf32(acc[jn], ah, bh);
            }
        }
        __syncthreads();
    }

    // epilogue: acc -> hyperbolic arg
    const int q0 = qbase + qw + g;
    const int q1 = q0 + 8;
    const float qs0 = g_qsq[q0], qs1 = g_qsq[q1];
    const float qa0 = 1.0f - qs0, qa1 = 1.0f - qs1;
#pragma unroll
    for (int jn = 0; jn < 8; jn++) {
        int m0 = mb + nw + jn * 8 + 2 * tig;
        if (m0 < N_) {   // m0 even, N_ even -> m0+1 also valid
            float2 ms = *reinterpret_cast<const float2*>(g_msq + m0);
            float max_ = 1.0f - ms.x, may_ = 1.0f - ms.y;
            float2 o0, o1;
            {
                float diff = fmaxf(qs0 + ms.x - 2.0f * acc[jn][0], 0.0f);
                o0.x = 1.0f + (2.0f * diff) / (qa0 * max_ + 1e-8f);
                diff = fmaxf(qs0 + ms.y - 2.0f * acc[jn][1], 0.0f);
                o0.y = 1.0f + (2.0f * diff) / (qa0 * may_ + 1e-8f);
            }
            {
                float diff = fmaxf(qs1 + ms.x - 2.0f * acc[jn][2], 0.0f);
                o1.x = 1.0f + (2.0f * diff) / (qa1 * max_ + 1e-8f);
                diff = fmaxf(qs1 + ms.y - 2.0f * acc[jn][3], 0.0f);
                o1.y = 1.0f + (2.0f * diff) / (qa1 * may_ + 1e-8f);
            }
            *reinterpret_cast<float2*>(g_arg + (size_t)q0 * N_ + m0) = o0;
            *reinterpret_cast<float2*>(g_arg + (size_t)q1 * N_ + m0) = o1;
        }
    }
}

// ================= kernel 4: per-query top-8, softmax, gather =================
__global__ void __launch_bounds__(256) k_topk(const float* __restrict__ masks,
                                              float* __restrict__ out) {
    const int q = blockIdx.x, tid = threadIdx.x;
    const float4* __restrict__ row4 =
        reinterpret_cast<const float4*>(g_arg + (size_t)q * N_);

    unsigned long long best[K_];
#pragma unroll
    for (int s = 0; s < K_; s++) best[s] = 0x7F800000FFFFFFFFull;
    float bmax = __int_as_float(0x7F800000);

    for (int i = tid; i < N_ / 4; i += 256) {
        float4 a = row4[i];
        float av[4] = {a.x, a.y, a.z, a.w};
#pragma unroll
        for (int c = 0; c < 4; c++) {
            if (av[c] <= bmax) {
                unsigned long long key =
                    ((unsigned long long)__float_as_uint(av[c]) << 32) | (unsigned)(4 * i + c);
                if (key < best[K_ - 1]) {
                    best[K_ - 1] = key;
#pragma unroll
                    for (int s = K_ - 1; s > 0; s--) {
                        if (best[s] < best[s - 1]) {
                            unsigned long long t = best[s]; best[s] = best[s - 1]; best[s - 1] = t;
                        }
                    }
                    bmax = __uint_as_float((unsigned)(best[K_ - 1] >> 32));
                }
            }
        }
    }

    __shared__ unsigned long long red[8];
    __shared__ unsigned long long wks;
    __shared__ float sarg[K_];
    __shared__ int sidx[K_];

    for (int s = 0; s < K_; s++) {
        unsigned long long lm = best[0];
#pragma unroll
        for (int o = 16; o; o >>= 1)
            lm = umin64(lm, __shfl_xor_sync(0xffffffffu, lm, o));
        if ((tid & 31) == 0) red[tid >> 5] = lm;
        __syncthreads();
        if (tid == 0) {
            unsigned long long m = red[0];
#pragma unroll
            for (int i = 1; i < 8; i++) m = umin64(m, red[i]);
            wks = m;
            sarg[s] = __uint_as_float((unsigned)(m >> 32));
            sidx[s] = (int)(unsigned)(m & 0xffffffffu);
        }
        __syncthreads();
        if (best[0] == wks) {
#pragma unroll
            for (int i = 0; i < K_ - 1; i++) best[i] = best[i + 1];
            best[K_ - 1] = 0x7F800000FFFFFFFFull;
        }
        __syncthreads();
    }

    if (tid == 0) {
        float d[K_], w[K_], sum = 0.0f;
#pragma unroll
        for (int s = 0; s < K_; s++)
            d[s] = acoshf(fmaxf(sarg[s], 1.0f + 1e-6f));
#pragma unroll
        for (int s = 0; s < K_; s++) { w[s] = expf(d[0] - d[s]); sum += w[s]; }
#pragma unroll
        for (int s = 0; s < K_; s++)
            out[(size_t)q * K_ + s] = w[s] / sum;
    }
    __syncthreads();

    float* __restrict__ hints = out + (size_t)B_ * K_;
    for (int s = 0; s < K_; s++) {
        const float* __restrict__ src = masks + (size_t)sidx[s] * MA_;
        float* __restrict__ dst = hints + ((size_t)q * K_ + s) * MA_;
        for (int t = tid; t < MA_; t += 256) dst[t] = src[t];
    }
}

extern "C" void kernel_launch(void* const* d_in, const int* in_sizes, int n_in,
                              void* d_out, int out_size) {
    const float* q_emb  = (const float*)d_in[0];
    const float* m_emb  = (const float*)d_in[1];
    const float* masks  = (const float*)d_in[2];
    const float* W      = (const float*)d_in[3];
    const float* b      = (const float*)d_in[4];
    float* out = (float*)d_out;

    k_transform<<<dim3(B_ / 64, 2), 256>>>(q_emb, W, b, B_, 0);
    k_transform<<<dim3((N_ + 63) / 64, 2), 256>>>(m_emb, W, b, N_, 1);
    k_normalize<<<(B_ + 7) / 8, 256>>>(0, B_);
    k_normalize<<<(N_ + 7) / 8, 256>>>(1, N_);
    k_dist_mma<<<dim3(B_ / 64, (N_ + 127) / 128), 256>>>();
    k_topk<<<B_, 256>>>(masks, out);
}

// round 10
// speedup vs baseline: 1.5077x; 1.5077x over previous
#include <cuda_runtime.h>
#include <cfloat>
#include <math.h>
#include <stdint.h>

#define B_   1024
#define N_   50000
#define D_   256
#define MA_  200
#define K_   8
#define CAND 16

// ---------- device scratch ----------
__device__ float g_qh[B_ * D_];
__device__ float g_mh[(size_t)N_ * D_];
__device__ float g_qhh[B_ * D_];                 // tf32-rounded (approx pass)
__device__ float g_mhh[(size_t)N_ * D_];
__device__ float g_qsq[B_];
__device__ float g_msq[N_];
__device__ float g_arg[(size_t)B_ * N_];         // approx args, ~195 MB

// ---------- helpers ----------
__device__ __forceinline__ unsigned long long pk2(float x, float y) {
    unsigned long long u;
    asm("mov.b64 %0, {%1,%2};" : "=l"(u) : "f"(x), "f"(y));
    return u;
}
__device__ __forceinline__ float2 up2(unsigned long long u) {
    float2 v;
    asm("mov.b64 {%0,%1}, %2;" : "=f"(v.x), "=f"(v.y) : "l"(u));
    return v;
}
__device__ __forceinline__ void fma2(unsigned long long& c, unsigned long long a,
                                     unsigned long long b) {
    asm("fma.rn.f32x2 %0, %1, %2, %3;" : "=l"(c) : "l"(a), "l"(b), "l"(c));
}
__device__ __forceinline__ unsigned long long umin64(unsigned long long a,
                                                     unsigned long long b) {
    return a < b ? a : b;
}
__device__ __forceinline__ float tf32r(float x) {
    float r;
    asm("cvt.rna.tf32.f32 %0, %1;" : "=f"(r) : "f"(x));
    return r;
}
// D = A(16x8 tf32, row) @ B(8x8 tf32, col) + D, fp32 accum
__device__ __forceinline__ void mma_tf32(float* d, const float* a, const float* b) {
    asm volatile(
        "mma.sync.aligned.m16n8k8.row.col.f32.tf32.tf32.f32 "
        "{%0,%1,%2,%3}, {%4,%5,%6,%7}, {%8,%9}, {%0,%1,%2,%3};"
        : "+f"(d[0]), "+f"(d[1]), "+f"(d[2]), "+f"(d[3])
        : "f"(a[0]), "f"(a[1]), "f"(a[2]), "f"(a[3]), "f"(b[0]), "f"(b[1]));
}

// fp32 micro-kernel for transform (8q x 4c per thread)
#define MICRO_KK(kk)                                                          \
    {                                                                         \
        float4 q0 = *reinterpret_cast<const float4*>(&As[(kk) * 64 + w8]);    \
        float4 q1 = *reinterpret_cast<const float4*>(&As[(kk) * 64 + w8 + 4]);\
        ulonglong2 b = *reinterpret_cast<const ulonglong2*>(&Bs[(kk) * 128 + lane4]); \
        unsigned long long a0 = pk2(q0.x, q0.x), a1 = pk2(q0.y, q0.y);        \
        unsigned long long a2 = pk2(q0.z, q0.z), a3 = pk2(q0.w, q0.w);        \
        unsigned long long a4 = pk2(q1.x, q1.x), a5 = pk2(q1.y, q1.y);        \
        unsigned long long a6 = pk2(q1.z, q1.z), a7 = pk2(q1.w, q1.w);        \
        fma2(acc[0][0], a0, b.x); fma2(acc[0][1], a0, b.y);                   \
        fma2(acc[1][0], a1, b.x); fma2(acc[1][1], a1, b.y);                   \
        fma2(acc[2][0], a2, b.x); fma2(acc[2][1], a2, b.y);                   \
        fma2(acc[3][0], a3, b.x); fma2(acc[3][1], a3, b.y);                   \
        fma2(acc[4][0], a4, b.x); fma2(acc[4][1], a4, b.y);                   \
        fma2(acc[5][0], a5, b.x); fma2(acc[5][1], a5, b.y);                   \
        fma2(acc[6][0], a6, b.x); fma2(acc[6][1], a6, b.y);                   \
        fma2(acc[7][0], a7, b.x); fma2(acc[7][1], a7, b.y);                   \
    }

// ================= kernel 1: h = tanh(X @ W + b)  (fp32) =================
__global__ void __launch_bounds__(256, 2) k_transform(const float* __restrict__ A,
                                                      const float* __restrict__ W,
                                                      const float* __restrict__ bias,
                                                      int M, int to_mem) {
    __shared__ __align__(16) float As[32 * 64];
    __shared__ __align__(16) float Bs[32 * 128];
    float* __restrict__ out = to_mem ? g_mh : g_qh;

    const int tid = threadIdx.x;
    const int w8 = (tid >> 5) * 8;
    const int lane4 = (tid & 31) * 4;
    const int rbase = blockIdx.x * 64;
    const int cbase = blockIdx.y * 128;

    unsigned long long acc[8][2];
#pragma unroll
    for (int i = 0; i < 8; i++) { acc[i][0] = 0ull; acc[i][1] = 0ull; }

    const int sr = tid & 63;
    const int skq = tid >> 6;
    const int wkw = tid >> 3;
    const int wcs = (tid & 7) * 16;

    for (int ko = 0; ko < D_; ko += 32) {
        {
            int gr = rbase + sr;
            float4 v0 = {0,0,0,0}, v1 = {0,0,0,0};
            if (gr < M) {
                const float4* p = reinterpret_cast<const float4*>(A + (size_t)gr * D_ + ko + skq * 8);
                v0 = p[0]; v1 = p[1];
            }
            float vv[8] = {v0.x,v0.y,v0.z,v0.w,v1.x,v1.y,v1.z,v1.w};
#pragma unroll
            for (int i = 0; i < 8; i++) As[(skq * 8 + i) * 64 + sr] = vv[i];
        }
        {
            const float4* p = reinterpret_cast<const float4*>(W + (size_t)(ko + wkw) * D_ + cbase + wcs);
            float4 w0 = p[0], w1 = p[1], w2 = p[2], w3 = p[3];
            float4* q = reinterpret_cast<float4*>(&Bs[wkw * 128 + wcs]);
            q[0] = w0; q[1] = w1; q[2] = w2; q[3] = w3;
        }
        __syncthreads();
#pragma unroll
        for (int kk = 0; kk < 32; kk++) MICRO_KK(kk)
        __syncthreads();
    }

    const int c0 = cbase + lane4;
    float4 b4 = *reinterpret_cast<const float4*>(bias + c0);
#pragma unroll
    for (int i = 0; i < 8; i++) {
        int r = rbase + w8 + i;
        if (r < M) {
            float2 v0 = up2(acc[i][0]), v1 = up2(acc[i][1]);
            float4 o;
            o.x = tanhf(v0.x + b4.x); o.y = tanhf(v0.y + b4.y);
            o.z = tanhf(v1.x + b4.z); o.w = tanhf(v1.y + b4.w);
            *reinterpret_cast<float4*>(out + (size_t)r * D_ + c0) = o;
        }
    }
}

// ========== kernel 2: Poincare rescale (in place) + sumsq + tf32 round ==========
__global__ void __launch_bounds__(256) k_normalize(int which, int M) {
    float* __restrict__ h  = which ? g_mh  : g_qh;
    float* __restrict__ sq = which ? g_msq : g_qsq;
    float* __restrict__ hh = which ? g_mhh : g_qhh;
    int row = blockIdx.x * 8 + (threadIdx.x >> 5);
    if (row >= M) return;
    int lane = threadIdx.x & 31;
    size_t off = (size_t)row * D_ + lane * 8;
    float4* p = reinterpret_cast<float4*>(h + off);
    float4 v0 = p[0], v1 = p[1];
    float s = v0.x*v0.x + v0.y*v0.y + v0.z*v0.z + v0.w*v0.w
            + v1.x*v1.x + v1.y*v1.y + v1.z*v1.z + v1.w*v1.w;
#pragma unroll
    for (int o = 16; o; o >>= 1) s += __shfl_xor_sync(0xffffffffu, s, o);
    float norm = sqrtf(s);
    float scale = (norm > 0.95f) ? (0.95f / norm) : 1.0f;
    float y[8] = {v0.x*scale, v0.y*scale, v0.z*scale, v0.w*scale,
                  v1.x*scale, v1.y*scale, v1.z*scale, v1.w*scale};
    p[0] = make_float4(y[0], y[1], y[2], y[3]);
    p[1] = make_float4(y[4], y[5], y[6], y[7]);
    float hi[8];
    float s2 = 0.0f;
#pragma unroll
    for (int i = 0; i < 8; i++) {
        s2 += y[i] * y[i];
        hi[i] = tf32r(y[i]);
    }
#pragma unroll
    for (int o = 16; o; o >>= 1) s2 += __shfl_xor_sync(0xffffffffu, s2, o);
    if (lane == 0) sq[row] = s2;
    float4* ph = reinterpret_cast<float4*>(hh + off);
    ph[0] = make_float4(hi[0],hi[1],hi[2],hi[3]);
    ph[1] = make_float4(hi[4],hi[5],hi[6],hi[7]);
}

// ========== kernel 3: approx distance GEMM (single-pass tf32 mma.sync) ==========
// block 64q x 128m; 8 warps = 4 q-groups x 2 m-groups; warp = 16q x 64m.
// smem holds (k,k+4) float2 pairs so fragments load as LDS.64, conflict-free.
__global__ void __launch_bounds__(256) k_dist_mma() {
    __shared__ __align__(16) float2 Ap[4 * 64 * 4];    // [ks][q][tig]  8 KB
    __shared__ __align__(16) float2 Mp[4 * 128 * 4];   // [ks][m][tig] 16 KB

    const int tid = threadIdx.x;
    const int warp = tid >> 5, lane = tid & 31;
    const int g = lane >> 2, tig = lane & 3;
    const int qw = (warp & 3) * 16;
    const int nw = (warp >> 2) * 64;
    const int qbase = blockIdx.x * 64;
    const int mb = blockIdx.y * 128;

    float acc[8][4];
#pragma unroll
    for (int j = 0; j < 8; j++)
#pragma unroll
        for (int c = 0; c < 4; c++) acc[j][c] = 0.0f;

    const int sq_ = tid & 63, sks = tid >> 6;   // Q staging: row, k-group

    for (int ko = 0; ko < D_; ko += 32) {
        {   // Q tile: 64 rows x 32 k -> pairs
            const float4* p = reinterpret_cast<const float4*>(
                g_qhh + (size_t)(qbase + sq_) * D_ + ko + sks * 8);
            float4 v0 = p[0], v1 = p[1];
            float4* d = reinterpret_cast<float4*>(&Ap[(sks * 64 + sq_) * 4]);
            d[0] = make_float4(v0.x, v1.x, v0.y, v1.y);
            d[1] = make_float4(v0.z, v1.z, v0.w, v1.w);
        }
#pragma unroll
        for (int it = 0; it < 2; it++) {   // M tile: 128 rows x 32 k -> pairs
            int idx = tid + 256 * it;
            int r = idx & 127, ks = idx >> 7;
            int gm = mb + r;
            float4 v0 = {0,0,0,0}, v1 = {0,0,0,0};
            if (gm < N_) {
                const float4* p = reinterpret_cast<const float4*>(
                    g_mhh + (size_t)gm * D_ + ko + ks * 8);
                v0 = p[0]; v1 = p[1];
            }
            float4* d = reinterpret_cast<float4*>(&Mp[(ks * 128 + r) * 4]);
            d[0] = make_float4(v0.x, v1.x, v0.y, v1.y);
            d[1] = make_float4(v0.z, v1.z, v0.w, v1.w);
        }
        __syncthreads();
#pragma unroll
        for (int ks = 0; ks < 4; ks++) {
            float2 ap0 = Ap[(ks * 64 + qw + g) * 4 + tig];
            float2 ap1 = Ap[(ks * 64 + qw + g + 8) * 4 + tig];
            float a[4] = {ap0.x, ap1.x, ap0.y, ap1.y};
#pragma unroll
            for (int jn = 0; jn < 8; jn++) {
                float2 bp = Mp[(ks * 128 + nw + jn * 8 + g) * 4 + tig];
                float b[2] = {bp.x, bp.y};
                mma_tf32(acc[jn], a, b);
            }
        }
        __syncthreads();
    }

    // epilogue: approx hyperbolic arg -> g_arg
    const int q0 = qbase + qw + g;
    const int q1 = q0 + 8;
    const float qs0 = g_qsq[q0], qs1 = g_qsq[q1];
    const float qa0 = 1.0f - qs0, qa1 = 1.0f - qs1;
#pragma unroll
    for (int jn = 0; jn < 8; jn++) {
        int m0 = mb + nw + jn * 8 + 2 * tig;
        if (m0 < N_) {   // m0 even, N_ even -> m0+1 also valid
            float2 ms = *reinterpret_cast<const float2*>(g_msq + m0);
            float max_ = 1.0f - ms.x, may_ = 1.0f - ms.y;
            float2 o0, o1;
            float diff = fmaxf(qs0 + ms.x - 2.0f * acc[jn][0], 0.0f);
            o0.x = 1.0f + (2.0f * diff) / (qa0 * max_ + 1e-8f);
            diff = fmaxf(qs0 + ms.y - 2.0f * acc[jn][1], 0.0f);
            o0.y = 1.0f + (2.0f * diff) / (qa0 * may_ + 1e-8f);
            diff = fmaxf(qs1 + ms.x - 2.0f * acc[jn][2], 0.0f);
            o1.x = 1.0f + (2.0f * diff) / (qa1 * max_ + 1e-8f);
            diff = fmaxf(qs1 + ms.y - 2.0f * acc[jn][3], 0.0f);
            o1.y = 1.0f + (2.0f * diff) / (qa1 * may_ + 1e-8f);
            *reinterpret_cast<float2*>(g_arg + (size_t)q0 * N_ + m0) = o0;
            *reinterpret_cast<float2*>(g_arg + (size_t)q1 * N_ + m0) = o1;
        }
    }
}

// ===== kernel 4: approx top-16 candidates -> exact re-rank -> top-8 =====
__global__ void __launch_bounds__(256) k_topk(const float* __restrict__ masks,
                                              float* __restrict__ out) {
    const int q = blockIdx.x, tid = threadIdx.x;
    const int wid = tid >> 5, lane = tid & 31;
    const float4* __restrict__ row4 =
        reinterpret_cast<const float4*>(g_arg + (size_t)q * N_);

    // phase 1: per-thread top-8 on approx keys
    unsigned long long best[K_];
#pragma unroll
    for (int s = 0; s < K_; s++) best[s] = 0x7F800000FFFFFFFFull;
    float bmax = __int_as_float(0x7F800000);

    for (int i = tid; i < N_ / 4; i += 256) {
        float4 a = row4[i];
        float av[4] = {a.x, a.y, a.z, a.w};
#pragma unroll
        for (int c = 0; c < 4; c++) {
            if (av[c] <= bmax) {
                unsigned long long key =
                    ((unsigned long long)__float_as_uint(av[c]) << 32) | (unsigned)(4 * i + c);
                if (key < best[K_ - 1]) {
                    best[K_ - 1] = key;
#pragma unroll
                    for (int s = K_ - 1; s > 0; s--) {
                        if (best[s] < best[s - 1]) {
                            unsigned long long t = best[s]; best[s] = best[s - 1]; best[s - 1] = t;
                        }
                    }
                    bmax = __uint_as_float((unsigned)(best[K_ - 1] >> 32));
                }
            }
        }
    }

    // phase 2: extract CAND=16 block-wide smallest approx keys
    __shared__ unsigned long long red[8];
    __shared__ unsigned long long wks;
    __shared__ int cidx[CAND];
    __shared__ unsigned long long ekeys[CAND];
    __shared__ int fidx[K_];

    for (int s = 0; s < CAND; s++) {
        unsigned long long lm = best[0];
#pragma unroll
        for (int o = 16; o; o >>= 1)
            lm = umin64(lm, __shfl_xor_sync(0xffffffffu, lm, o));
        if (lane == 0) red[wid] = lm;
        __syncthreads();
        if (tid == 0) {
            unsigned long long m = red[0];
#pragma unroll
            for (int i = 1; i < 8; i++) m = umin64(m, red[i]);
            wks = m;
            cidx[s] = (int)(unsigned)(m & 0xffffffffu);
        }
        __syncthreads();
        if (best[0] == wks) {
#pragma unroll
            for (int i = 0; i < K_ - 1; i++) best[i] = best[i + 1];
            best[K_ - 1] = 0x7F800000FFFFFFFFull;
        }
        __syncthreads();
    }

    // phase 3: exact fp32 re-rank of 16 candidates (one per warp, 2 rounds)
    const float4* qp = reinterpret_cast<const float4*>(g_qh + (size_t)q * D_ + lane * 8);
    float4 a0 = qp[0], a1 = qp[1];
    const float qs = g_qsq[q];
    const float qa = 1.0f - qs;
#pragma unroll
    for (int r = 0; r < 2; r++) {
        int c = wid + 8 * r;
        int idx = cidx[c];
        const float4* mp = reinterpret_cast<const float4*>(g_mh + (size_t)idx * D_ + lane * 8);
        float4 b0 = mp[0], b1 = mp[1];
        float dot = a0.x*b0.x + a0.y*b0.y + a0.z*b0.z + a0.w*b0.w
                  + a1.x*b1.x + a1.y*b1.y + a1.z*b1.z + a1.w*b1.w;
#pragma unroll
        for (int o = 16; o; o >>= 1) dot += __shfl_xor_sync(0xffffffffu, dot, o);
        if (lane == 0) {
            float ms = g_msq[idx];
            float diff = fmaxf(qs + ms - 2.0f * dot, 0.0f);
            float arg = 1.0f + (2.0f * diff) / (qa * (1.0f - ms) + 1e-8f);
            ekeys[c] = ((unsigned long long)__float_as_uint(arg) << 32) | (unsigned)idx;
        }
    }
    __syncthreads();

    // phase 4: exact top-8 of 16, softmax
    if (tid == 0) {
        unsigned long long k[CAND];
#pragma unroll
        for (int i = 0; i < CAND; i++) k[i] = ekeys[i];
#pragma unroll
        for (int i = 1; i < CAND; i++) {      // insertion sort ascending
            unsigned long long x = k[i];
            int j = i - 1;
            while (j >= 0 && k[j] > x) { k[j + 1] = k[j]; j--; }
            k[j + 1] = x;
        }
        float d[K_], w[K_], sum = 0.0f;
#pragma unroll
        for (int s = 0; s < K_; s++) {
            float arg = __uint_as_float((unsigned)(k[s] >> 32));
            d[s] = acoshf(fmaxf(arg, 1.0f + 1e-6f));
            fidx[s] = (int)(unsigned)(k[s] & 0xffffffffu);
        }
#pragma unroll
        for (int s = 0; s < K_; s++) { w[s] = expf(d[0] - d[s]); sum += w[s]; }
#pragma unroll
        for (int s = 0; s < K_; s++)
            out[(size_t)q * K_ + s] = w[s] / sum;
    }
    __syncthreads();

    // phase 5: gather som_hints
    float* __restrict__ hints = out + (size_t)B_ * K_;
    for (int s = 0; s < K_; s++) {
        const float* __restrict__ src = masks + (size_t)fidx[s] * MA_;
        float* __restrict__ dst = hints + ((size_t)q * K_ + s) * MA_;
        for (int t = tid; t < MA_; t += 256) dst[t] = src[t];
    }
}

extern "C" void kernel_launch(void* const* d_in, const int* in_sizes, int n_in,
                              void* d_out, int out_size) {
    const float* q_emb  = (const float*)d_in[0];
    const float* m_emb  = (const float*)d_in[1];
    const float* masks  = (const float*)d_in[2];
    const float* W      = (const float*)d_in[3];
    const float* b      = (const float*)d_in[4];
    float* out = (float*)d_out;

    k_transform<<<dim3(B_ / 64, 2), 256>>>(q_emb, W, b, B_, 0);
    k_transform<<<dim3((N_ + 63) / 64, 2), 256>>>(m_emb, W, b, N_, 1);
    k_normalize<<<(B_ + 7) / 8, 256>>>(0, B_);
    k_normalize<<<(N_ + 7) / 8, 256>>>(1, N_);
    k_dist_mma<<<dim3(B_ / 64, (N_ + 127) / 128), 256>>>();
    k_topk<<<B_, 256>>>(masks, out);
}

// round 11
// speedup vs baseline: 2.5606x; 1.6984x over previous
#include <cuda_runtime.h>
#include <cuda_bf16.h>
#include <cfloat>
#include <math.h>
#include <stdint.h>

#define B_   1024
#define N_   50000
#define D_   256
#define MA_  200
#define K_   8
#define CAND 16
#define TILES 391              // ceil(50000/128)

// ---------- device scratch ----------
__device__ float g_qh[B_ * D_];                    // exact fp32 (rescaled)
__device__ float g_mh[(size_t)N_ * D_];
__device__ uint32_t g_qhb[B_ * D_ / 2];            // bf16 pairs for filter
__device__ uint32_t g_mhb[(size_t)N_ * D_ / 2];
__device__ float g_qsq[B_];
__device__ float g_msq[N_];
__device__ uint32_t g_cand[(size_t)B_ * TILES * 24];   // 38.4 MB

// ---------- helpers ----------
__device__ __forceinline__ unsigned long long pk2(float x, float y) {
    unsigned long long u;
    asm("mov.b64 %0, {%1,%2};" : "=l"(u) : "f"(x), "f"(y));
    return u;
}
__device__ __forceinline__ float2 up2(unsigned long long u) {
    float2 v;
    asm("mov.b64 {%0,%1}, %2;" : "=f"(v.x), "=f"(v.y) : "l"(u));
    return v;
}
__device__ __forceinline__ void fma2(unsigned long long& c, unsigned long long a,
                                     unsigned long long b) {
    asm("fma.rn.f32x2 %0, %1, %2, %3;" : "=l"(c) : "l"(a), "l"(b), "l"(c));
}
__device__ __forceinline__ unsigned long long umin64(unsigned long long a,
                                                     unsigned long long b) {
    return a < b ? a : b;
}
__device__ __forceinline__ uint32_t umin32(uint32_t a, uint32_t b) { return a < b ? a : b; }

// D += A(16x16 bf16, row) @ B(16x8 bf16, col), fp32 accum
__device__ __forceinline__ void mma_bf16(float* d, uint32_t a0, uint32_t a1,
                                         uint32_t a2, uint32_t a3,
                                         uint32_t b0, uint32_t b1) {
    asm volatile(
        "mma.sync.aligned.m16n8k16.row.col.f32.bf16.bf16.f32 "
        "{%0,%1,%2,%3}, {%4,%5,%6,%7}, {%8,%9}, {%0,%1,%2,%3};"
        : "+f"(d[0]), "+f"(d[1]), "+f"(d[2]), "+f"(d[3])
        : "r"(a0), "r"(a1), "r"(a2), "r"(a3), "r"(b0), "r"(b1));
}

// fp32 micro-kernel for transform (8q x 4c per thread)
#define MICRO_KK(kk)                                                          \
    {                                                                         \
        float4 q0 = *reinterpret_cast<const float4*>(&As[(kk) * 64 + w8]);    \
        float4 q1 = *reinterpret_cast<const float4*>(&As[(kk) * 64 + w8 + 4]);\
        ulonglong2 b = *reinterpret_cast<const ulonglong2*>(&Bs[(kk) * 128 + lane4]); \
        unsigned long long a0 = pk2(q0.x, q0.x), a1 = pk2(q0.y, q0.y);        \
        unsigned long long a2 = pk2(q0.z, q0.z), a3 = pk2(q0.w, q0.w);        \
        unsigned long long a4 = pk2(q1.x, q1.x), a5 = pk2(q1.y, q1.y);        \
        unsigned long long a6 = pk2(q1.z, q1.z), a7 = pk2(q1.w, q1.w);        \
        fma2(acc[0][0], a0, b.x); fma2(acc[0][1], a0, b.y);                   \
        fma2(acc[1][0], a1, b.x); fma2(acc[1][1], a1, b.y);                   \
        fma2(acc[2][0], a2, b.x); fma2(acc[2][1], a2, b.y);                   \
        fma2(acc[3][0], a3, b.x); fma2(acc[3][1], a3, b.y);                   \
        fma2(acc[4][0], a4, b.x); fma2(acc[4][1], a4, b.y);                   \
        fma2(acc[5][0], a5, b.x); fma2(acc[5][1], a5, b.y);                   \
        fma2(acc[6][0], a6, b.x); fma2(acc[6][1], a6, b.y);                   \
        fma2(acc[7][0], a7, b.x); fma2(acc[7][1], a7, b.y);                   \
    }

// ================= kernel 1: h = tanh(X @ W + b)  (fp32) =================
__global__ void __launch_bounds__(256, 2) k_transform(const float* __restrict__ A,
                                                      const float* __restrict__ W,
                                                      const float* __restrict__ bias,
                                                      int M, int to_mem) {
    __shared__ __align__(16) float As[32 * 64];
    __shared__ __align__(16) float Bs[32 * 128];
    float* __restrict__ out = to_mem ? g_mh : g_qh;

    const int tid = threadIdx.x;
    const int w8 = (tid >> 5) * 8;
    const int lane4 = (tid & 31) * 4;
    const int rbase = blockIdx.x * 64;
    const int cbase = blockIdx.y * 128;

    unsigned long long acc[8][2];
#pragma unroll
    for (int i = 0; i < 8; i++) { acc[i][0] = 0ull; acc[i][1] = 0ull; }

    const int sr = tid & 63;
    const int skq = tid >> 6;
    const int wkw = tid >> 3;
    const int wcs = (tid & 7) * 16;

    for (int ko = 0; ko < D_; ko += 32) {
        {
            int gr = rbase + sr;
            float4 v0 = {0,0,0,0}, v1 = {0,0,0,0};
            if (gr < M) {
                const float4* p = reinterpret_cast<const float4*>(A + (size_t)gr * D_ + ko + skq * 8);
                v0 = p[0]; v1 = p[1];
            }
            float vv[8] = {v0.x,v0.y,v0.z,v0.w,v1.x,v1.y,v1.z,v1.w};
#pragma unroll
            for (int i = 0; i < 8; i++) As[(skq * 8 + i) * 64 + sr] = vv[i];
        }
        {
            const float4* p = reinterpret_cast<const float4*>(W + (size_t)(ko + wkw) * D_ + cbase + wcs);
            float4 w0 = p[0], w1 = p[1], w2 = p[2], w3 = p[3];
            float4* q = reinterpret_cast<float4*>(&Bs[wkw * 128 + wcs]);
            q[0] = w0; q[1] = w1; q[2] = w2; q[3] = w3;
        }
        __syncthreads();
#pragma unroll
        for (int kk = 0; kk < 32; kk++) MICRO_KK(kk)
        __syncthreads();
    }

    const int c0 = cbase + lane4;
    float4 b4 = *reinterpret_cast<const float4*>(bias + c0);
#pragma unroll
    for (int i = 0; i < 8; i++) {
        int r = rbase + w8 + i;
        if (r < M) {
            float2 v0 = up2(acc[i][0]), v1 = up2(acc[i][1]);
            float4 o;
            o.x = tanhf(v0.x + b4.x); o.y = tanhf(v0.y + b4.y);
            o.z = tanhf(v1.x + b4.z); o.w = tanhf(v1.y + b4.w);
            *reinterpret_cast<float4*>(out + (size_t)r * D_ + c0) = o;
        }
    }
}

// ==== kernel 2: Poincare rescale (in place) + sumsq + bf16 pack ====
__global__ void __launch_bounds__(256) k_normalize(int which, int M) {
    float* __restrict__ h  = which ? g_mh  : g_qh;
    float* __restrict__ sq = which ? g_msq : g_qsq;
    uint32_t* __restrict__ hb = which ? g_mhb : g_qhb;
    int row = blockIdx.x * 8 + (threadIdx.x >> 5);
    if (row >= M) return;
    int lane = threadIdx.x & 31;
    size_t off = (size_t)row * D_ + lane * 8;
    float4* p = reinterpret_cast<float4*>(h + off);
    float4 v0 = p[0], v1 = p[1];
    float s = v0.x*v0.x + v0.y*v0.y + v0.z*v0.z + v0.w*v0.w
            + v1.x*v1.x + v1.y*v1.y + v1.z*v1.z + v1.w*v1.w;
#pragma unroll
    for (int o = 16; o; o >>= 1) s += __shfl_xor_sync(0xffffffffu, s, o);
    float norm = sqrtf(s);
    float scale = (norm > 0.95f) ? (0.95f / norm) : 1.0f;
    float y[8] = {v0.x*scale, v0.y*scale, v0.z*scale, v0.w*scale,
                  v1.x*scale, v1.y*scale, v1.z*scale, v1.w*scale};
    p[0] = make_float4(y[0], y[1], y[2], y[3]);
    p[1] = make_float4(y[4], y[5], y[6], y[7]);
    float s2 = 0.0f;
#pragma unroll
    for (int i = 0; i < 8; i++) s2 += y[i] * y[i];
#pragma unroll
    for (int o = 16; o; o >>= 1) s2 += __shfl_xor_sync(0xffffffffu, s2, o);
    if (lane == 0) sq[row] = s2;
    // bf16 pack: word w = (bf16(y[2w]), bf16(y[2w+1]))
    uint32_t wds[4];
#pragma unroll
    for (int i = 0; i < 4; i++) {
        __nv_bfloat162 bb = __floats2bfloat162_rn(y[2*i], y[2*i+1]);
        wds[i] = *reinterpret_cast<uint32_t*>(&bb);
    }
    *reinterpret_cast<uint4*>(hb + (size_t)row * 128 + lane * 4) =
        make_uint4(wds[0], wds[1], wds[2], wds[3]);
}

// ==== kernel 3: bf16 filter GEMM + fused per-thread top-3 candidates ====
// block 64q x 128m; 8 warps = 4 qw x 2 nw; warp 16q x 64m; mma m16n8k16.
// smem dword = (word w, word w+4) so fragments load as conflict-free LDS.64.
__global__ void __launch_bounds__(256) k_dist_cand() {
    __shared__ __align__(16) uint2 Ap[4 * 64 * 4];     // [ks][qrow][tig]  8 KB
    __shared__ __align__(16) uint2 Mp[4 * 128 * 4];    // [ks][mrow][tig] 16 KB

    const int tid = threadIdx.x;
    const int warp = tid >> 5, lane = tid & 31;
    const int g = lane >> 2, tig = lane & 3;
    const int qw = (warp & 3) * 16;
    const int nwbit = warp >> 2;
    const int nw = nwbit * 64;
    const int qbase = blockIdx.x * 64;
    const int mb = blockIdx.y * 128;

    float acc[8][4];
#pragma unroll
    for (int j = 0; j < 8; j++)
#pragma unroll
        for (int c = 0; c < 4; c++) acc[j][c] = 0.0f;

    const int sq_ = tid & 63, sks = tid >> 6;

    for (int ch = 0; ch < 4; ch++) {            // 64-k chunks
        const int wb = ch * 32;                 // word base (k/2)
        {   // Q tile: 64 rows x 4 ks
            const uint4* p = reinterpret_cast<const uint4*>(
                g_qhb + (size_t)(qbase + sq_) * 128 + wb + sks * 8);
            uint4 u0 = p[0], u1 = p[1];
            uint2* d = &Ap[(sks * 64 + sq_) * 4];
            d[0] = make_uint2(u0.x, u1.x);
            d[1] = make_uint2(u0.y, u1.y);
            d[2] = make_uint2(u0.z, u1.z);
            d[3] = make_uint2(u0.w, u1.w);
        }
#pragma unroll
        for (int it = 0; it < 2; it++) {        // M tile: 128 rows x 4 ks
            int idx = tid + 256 * it;
            int r = idx & 127, ks = idx >> 7;
            int gm = mb + r;
            uint4 u0 = {0,0,0,0}, u1 = {0,0,0,0};
            if (gm < N_) {
                const uint4* p = reinterpret_cast<const uint4*>(
                    g_mhb + (size_t)gm * 128 + wb + ks * 8);
                u0 = p[0]; u1 = p[1];
            }
            uint2* d = &Mp[(ks * 128 + r) * 4];
            d[0] = make_uint2(u0.x, u1.x);
            d[1] = make_uint2(u0.y, u1.y);
            d[2] = make_uint2(u0.z, u1.z);
            d[3] = make_uint2(u0.w, u1.w);
        }
        __syncthreads();
#pragma unroll
        for (int ks = 0; ks < 4; ks++) {
            uint2 aA = Ap[(ks * 64 + qw + g) * 4 + tig];       // a0, a2
            uint2 aB = Ap[(ks * 64 + qw + g + 8) * 4 + tig];   // a1, a3
#pragma unroll
            for (int jn = 0; jn < 8; jn++) {
                uint2 bb = Mp[(ks * 128 + nw + jn * 8 + g) * 4 + tig];  // b0, b1
                mma_bf16(acc[jn], aA.x, aB.x, aA.y, aB.y, bb.x, bb.y);
            }
        }
        __syncthreads();
    }

    // epilogue: approx arg + per-thread top-3 (32-bit keys), per q-row
    const int q0 = qbase + qw + g;
#pragma unroll
    for (int i = 0; i < 2; i++) {
        const int qr = q0 + i * 8;
        const float qs = g_qsq[qr];
        const float qa = 1.0f - qs;
        uint32_t t0 = 0xFFFFFFFFu, t1 = 0xFFFFFFFFu, t2 = 0xFFFFFFFFu;
#pragma unroll
        for (int jn = 0; jn < 8; jn++) {
#pragma unroll
            for (int h = 0; h < 2; h++) {
                int m = mb + nw + jn * 8 + 2 * tig + h;
                if (m < N_) {
                    float ms = g_msq[m];
                    float dot = acc[jn][i * 2 + h];
                    float diff = fmaxf(qs + ms - 2.0f * dot, 0.0f);
                    float arg = 1.0f + (2.0f * diff) / (qa * (1.0f - ms) + 1e-8f);
                    uint32_t key = (__float_as_uint(arg) & 0xFFFF0000u) | (uint32_t)m;
                    if (key < t2) {
                        if (key < t1) {
                            t2 = t1;
                            if (key < t0) { t1 = t0; t0 = key; } else t1 = key;
                        } else t2 = key;
                    }
                }
            }
        }
        size_t base = ((size_t)qr * TILES + blockIdx.y) * 24 + (nwbit * 4 + tig) * 3;
        g_cand[base]     = t0;
        g_cand[base + 1] = t1;
        g_cand[base + 2] = t2;
    }
}

// ==== kernel 4: merge candidates -> approx top-16 -> exact re-rank -> out ====
__global__ void __launch_bounds__(256) k_merge(const float* __restrict__ masks,
                                               float* __restrict__ out) {
    const int q = blockIdx.x, tid = threadIdx.x;
    const int wid = tid >> 5, lane = tid & 31;
    const uint32_t* __restrict__ cand = g_cand + (size_t)q * (TILES * 24);
    const int TOT = TILES * 24;

    // per-thread top-6 of ~37 keys
    uint32_t best[6];
#pragma unroll
    for (int s = 0; s < 6; s++) best[s] = 0xFFFFFFFFu;
    for (int i = tid; i < TOT; i += 256) {
        uint32_t k = cand[i];
        if (k < best[5]) {
            best[5] = k;
#pragma unroll
            for (int s = 5; s > 0; s--) {
                if (best[s] < best[s - 1]) {
                    uint32_t t = best[s]; best[s] = best[s - 1]; best[s - 1] = t;
                }
            }
        }
    }

    __shared__ uint32_t red[8];
    __shared__ uint32_t wks;
    __shared__ int cidx[CAND];
    __shared__ unsigned long long ekeys[CAND];
    __shared__ int fidx[K_];

    // extract block-wide 16 smallest approx keys
    for (int s = 0; s < CAND; s++) {
        uint32_t lm = best[0];
#pragma unroll
        for (int o = 16; o; o >>= 1)
            lm = umin32(lm, __shfl_xor_sync(0xffffffffu, lm, o));
        if (lane == 0) red[wid] = lm;
        __syncthreads();
        if (tid == 0) {
            uint32_t m = red[0];
#pragma unroll
            for (int i = 1; i < 8; i++) m = umin32(m, red[i]);
            wks = m;
            cidx[s] = (int)(m & 0xFFFFu);
        }
        __syncthreads();
        if (best[0] == wks) {     // real keys unique (idx embedded)
#pragma unroll
            for (int i = 0; i < 5; i++) best[i] = best[i + 1];
            best[5] = 0xFFFFFFFFu;
        }
        __syncthreads();
    }

    // exact fp32 re-rank of 16 candidates (one per warp, 2 rounds)
    const float4* qp = reinterpret_cast<const float4*>(g_qh + (size_t)q * D_ + lane * 8);
    float4 a0 = qp[0], a1 = qp[1];
    const float qs = g_qsq[q];
    const float qa = 1.0f - qs;
#pragma unroll
    for (int r = 0; r < 2; r++) {
        int c = wid + 8 * r;
        int idx = cidx[c];
        const float4* mp = reinterpret_cast<const float4*>(g_mh + (size_t)idx * D_ + lane * 8);
        float4 b0 = mp[0], b1 = mp[1];
        float dot = a0.x*b0.x + a0.y*b0.y + a0.z*b0.z + a0.w*b0.w
                  + a1.x*b1.x + a1.y*b1.y + a1.z*b1.z + a1.w*b1.w;
#pragma unroll
        for (int o = 16; o; o >>= 1) dot += __shfl_xor_sync(0xffffffffu, dot, o);
        if (lane == 0) {
            float ms = g_msq[idx];
            float diff = fmaxf(qs + ms - 2.0f * dot, 0.0f);
            float arg = 1.0f + (2.0f * diff) / (qa * (1.0f - ms) + 1e-8f);
            ekeys[c] = ((unsigned long long)__float_as_uint(arg) << 32) | (unsigned)idx;
        }
    }
    __syncthreads();

    // exact top-8 of 16, softmax
    if (tid == 0) {
        unsigned long long k[CAND];
#pragma unroll
        for (int i = 0; i < CAND; i++) k[i] = ekeys[i];
#pragma unroll
        for (int i = 1; i < CAND; i++) {
            unsigned long long x = k[i];
            int j = i - 1;
            while (j >= 0 && k[j] > x) { k[j + 1] = k[j]; j--; }
            k[j + 1] = x;
        }
        float d[K_], w[K_], sum = 0.0f;
#pragma unroll
        for (int s = 0; s < K_; s++) {
            float arg = __uint_as_float((unsigned)(k[s] >> 32));
            d[s] = acoshf(fmaxf(arg, 1.0f + 1e-6f));
            fidx[s] = (int)(unsigned)(k[s] & 0xffffffffu);
        }
#pragma unroll
        for (int s = 0; s < K_; s++) { w[s] = expf(d[0] - d[s]); sum += w[s]; }
#pragma unroll
        for (int s = 0; s < K_; s++)
            out[(size_t)q * K_ + s] = w[s] / sum;
    }
    __syncthreads();

    // gather som_hints
    float* __restrict__ hints = out + (size_t)B_ * K_;
    for (int s = 0; s < K_; s++) {
        const float* __restrict__ src = masks + (size_t)fidx[s] * MA_;
        float* __restrict__ dst = hints + ((size_t)q * K_ + s) * MA_;
        for (int t = tid; t < MA_; t += 256) dst[t] = src[t];
    }
}

extern "C" void kernel_launch(void* const* d_in, const int* in_sizes, int n_in,
                              void* d_out, int out_size) {
    const float* q_emb  = (const float*)d_in[0];
    const float* m_emb  = (const float*)d_in[1];
    const float* masks  = (const float*)d_in[2];
    const float* W      = (const float*)d_in[3];
    const float* b      = (const float*)d_in[4];
    float* out = (float*)d_out;

    k_transform<<<dim3(B_ / 64, 2), 256>>>(q_emb, W, b, B_, 0);
    k_transform<<<dim3((N_ + 63) / 64, 2), 256>>>(m_emb, W, b, N_, 1);
    k_normalize<<<(B_ + 7) / 8, 256>>>(0, B_);
    k_normalize<<<(N_ + 7) / 8, 256>>>(1, N_);
    k_dist_cand<<<dim3(B_ / 64, TILES), 256>>>();
    k_merge<<<B_, 256>>>(masks, out);
}